// round 6
// baseline (speedup 1.0000x reference)
#include <cuda_runtime.h>

// Fused 5-point replicate-pad stencil + cubic Horner polynomial.
// R6: RPT=8 with shuffles moved into the compute loop (halo regs not held
// live) + __launch_bounds__(256,4) to cap at 64 regs -> 4 CTAs/SM.
// Goal: keep MLP=10 front-batched LDG.128 while restoring occupancy.

#define H_DIM 2048
#define W_DIM 2048
#define RPT   8   // rows per thread

__global__ void __launch_bounds__(256, 4) stencil_poly_8row(
    const float* __restrict__ x,
    const float* __restrict__ a,
    const float* __restrict__ w,
    float* __restrict__ out,
    int nplanes)
{
    const int W4 = W_DIM >> 2;          // 512
    const int HG = H_DIM / RPT;         // 256 row-groups

    long long tid = (long long)blockIdx.x * blockDim.x + threadIdx.x;
    long long total = (long long)nplanes * HG * W4;
    if (tid >= total) return;

    int c4 = (int)(tid % W4);
    long long t2 = tid / W4;
    int rg = (int)(t2 % HG);
    int p  = (int)(t2 / HG);

    int rbase = rg * RPT;

    const float* plane = x + (long long)p * H_DIM * W_DIM;

    // RPT+2 front-batched row loads: rbase-1 .. rbase+RPT, clamped at edges.
    int rtop = (rbase > 0) ? rbase - 1 : 0;
    int rbot = (rbase + RPT < H_DIM) ? rbase + RPT : H_DIM - 1;

    float4 v[RPT + 2];
    v[0] = __ldg((const float4*)(plane + (long long)rtop * W_DIM) + c4);
    #pragma unroll
    for (int i = 0; i < RPT; i++)
        v[i + 1] = __ldg((const float4*)(plane + (long long)(rbase + i) * W_DIM) + c4);
    v[RPT + 1] = __ldg((const float4*)(plane + (long long)rbot * W_DIM) + c4);

    int lane = threadIdx.x & 31;
    int c = c4 << 2;
    bool fix_l = (lane == 0);
    bool fix_r = (lane == 31);

    float a0 = __ldg(a + 0), a1 = __ldg(a + 1), a2 = __ldg(a + 2);
    float w0 = __ldg(w + 0), w1 = __ldg(w + 1), w2 = __ldg(w + 2), w3 = __ldg(w + 3);

    float* oplane = out + (long long)p * H_DIM * W_DIM;

    #pragma unroll
    for (int i = 0; i < RPT; i++) {
        float4 cv = v[i + 1];
        float4 up = v[i];
        float4 dn = v[i + 2];

        // horizontal halo for this row (warps are row-aligned: 512 % 32 == 0)
        float lh = __shfl_up_sync  (0xFFFFFFFFu, cv.w, 1);
        float rh = __shfl_down_sync(0xFFFFFFFFu, cv.x, 1);
        if (fix_l) {
            const float* row = plane + (long long)(rbase + i) * W_DIM;
            lh = (c == 0) ? cv.x : __ldg(row + c - 1);
        }
        if (fix_r) {
            const float* row = plane + (long long)(rbase + i) * W_DIM;
            rh = (c + 4 == W_DIM) ? cv.w : __ldg(row + c + 4);
        }

        float4 o;
        float xv = cv.x;
        o.x = a0*xv + a1*(lh   + cv.y) + a2*(up.x + dn.x)
            + fmaf(fmaf(fmaf(w3, xv, w2), xv, w1), xv, w0);
        xv = cv.y;
        o.y = a0*xv + a1*(cv.x + cv.z) + a2*(up.y + dn.y)
            + fmaf(fmaf(fmaf(w3, xv, w2), xv, w1), xv, w0);
        xv = cv.z;
        o.z = a0*xv + a1*(cv.y + cv.w) + a2*(up.z + dn.z)
            + fmaf(fmaf(fmaf(w3, xv, w2), xv, w1), xv, w0);
        xv = cv.w;
        o.w = a0*xv + a1*(cv.z + rh  ) + a2*(up.w + dn.w)
            + fmaf(fmaf(fmaf(w3, xv, w2), xv, w1), xv, w0);

        __stcs((float4*)(oplane + (long long)(rbase + i) * W_DIM) + c4, o);
    }
}

extern "C" void kernel_launch(void* const* d_in, const int* in_sizes, int n_in,
                              void* d_out, int out_size)
{
    const float* x = (const float*)d_in[0];
    const float* a = (const float*)d_in[1];
    const float* w = (const float*)d_in[2];
    float* out = (float*)d_out;

    int n = in_sizes[0];
    int nplanes = n / (H_DIM * W_DIM);  // B*C = 16

    long long total = (long long)nplanes * (H_DIM / RPT) * (W_DIM / 4);
    int threads = 256;
    long long blocks = (total + threads - 1) / threads;

    stencil_poly_8row<<<(unsigned)blocks, threads>>>(x, a, w, out, nplanes);
}

// round 7
// speedup vs baseline: 1.0388x; 1.0388x over previous
#include <cuda_runtime.h>

// Fused 5-point replicate-pad stencil + cubic Horner polynomial.
// R7: R4 (RPT=4, best harness config) with 3D grid (no div/mod) and
// 32-bit element indexing to cut ALU/front-end overhead.
//   grid.x = W4/256 = 2 (half-row of float4 columns)
//   grid.y = H/4   = 512 row-quads
//   grid.z = planes = 16

#define H_DIM 2048
#define W_DIM 2048
#define W4    (W_DIM / 4)   // 512
#define RPT   4             // rows per thread

__global__ void __launch_bounds__(256) stencil_poly_4row(
    const float* __restrict__ x,
    const float* __restrict__ a,
    const float* __restrict__ w,
    float* __restrict__ out)
{
    int c4    = blockIdx.x * 256 + threadIdx.x;   // 0..511
    int rbase = blockIdx.y << 2;                   // first of 4 rows
    int p     = blockIdx.z;

    // 32-bit element offsets: max 16*2048*2048 = 2^26*4 = 268M < 2^31
    int plane_off = p * (H_DIM * W_DIM);
    const float* plane = x + plane_off;

    int rtop = (rbase > 0) ? rbase - 1 : 0;
    int rbot = (rbase + 4 < H_DIM) ? rbase + 4 : H_DIM - 1;

    // 6 front-batched row loads (rbase-1 .. rbase+4, clamped)
    float4 v0 = __ldg((const float4*)(plane + rtop         * W_DIM) + c4);
    float4 v1 = __ldg((const float4*)(plane + (rbase    )  * W_DIM) + c4);
    float4 v2 = __ldg((const float4*)(plane + (rbase + 1)  * W_DIM) + c4);
    float4 v3 = __ldg((const float4*)(plane + (rbase + 2)  * W_DIM) + c4);
    float4 v4 = __ldg((const float4*)(plane + (rbase + 3)  * W_DIM) + c4);
    float4 v5 = __ldg((const float4*)(plane + rbot          * W_DIM) + c4);

    float4 v[6] = { v0, v1, v2, v3, v4, v5 };

    // horizontal halo via shuffle (warps are row-aligned: 512 % 32 == 0)
    int lane = threadIdx.x & 31;
    int c = c4 << 2;
    float lh[RPT], rh[RPT];
    #pragma unroll
    for (int i = 0; i < RPT; i++) {
        lh[i] = __shfl_up_sync  (0xFFFFFFFFu, v[i + 1].w, 1);
        rh[i] = __shfl_down_sync(0xFFFFFFFFu, v[i + 1].x, 1);
    }
    if (lane == 0) {
        #pragma unroll
        for (int i = 0; i < RPT; i++) {
            const float* row = plane + (rbase + i) * W_DIM;
            lh[i] = (c == 0) ? v[i + 1].x : __ldg(row + c - 1);
        }
    }
    if (lane == 31) {
        #pragma unroll
        for (int i = 0; i < RPT; i++) {
            const float* row = plane + (rbase + i) * W_DIM;
            rh[i] = (c + 4 == W_DIM) ? v[i + 1].w : __ldg(row + c + 4);
        }
    }

    float a0 = __ldg(a + 0), a1 = __ldg(a + 1), a2 = __ldg(a + 2);
    float w0 = __ldg(w + 0), w1 = __ldg(w + 1), w2 = __ldg(w + 2), w3 = __ldg(w + 3);

    float* oplane = out + plane_off;

    #pragma unroll
    for (int i = 0; i < RPT; i++) {
        float4 cv = v[i + 1];
        float4 up = v[i];
        float4 dn = v[i + 2];
        float4 o;

        float xv = cv.x;
        o.x = a0*xv + a1*(lh[i] + cv.y) + a2*(up.x + dn.x)
            + fmaf(fmaf(fmaf(w3, xv, w2), xv, w1), xv, w0);
        xv = cv.y;
        o.y = a0*xv + a1*(cv.x + cv.z) + a2*(up.y + dn.y)
            + fmaf(fmaf(fmaf(w3, xv, w2), xv, w1), xv, w0);
        xv = cv.z;
        o.z = a0*xv + a1*(cv.y + cv.w) + a2*(up.z + dn.z)
            + fmaf(fmaf(fmaf(w3, xv, w2), xv, w1), xv, w0);
        xv = cv.w;
        o.w = a0*xv + a1*(cv.z + rh[i]) + a2*(up.w + dn.w)
            + fmaf(fmaf(fmaf(w3, xv, w2), xv, w1), xv, w0);

        __stcs((float4*)(oplane + (rbase + i) * W_DIM) + c4, o);
    }
}

extern "C" void kernel_launch(void* const* d_in, const int* in_sizes, int n_in,
                              void* d_out, int out_size)
{
    const float* x = (const float*)d_in[0];
    const float* a = (const float*)d_in[1];
    const float* w = (const float*)d_in[2];
    float* out = (float*)d_out;

    int n = in_sizes[0];
    int nplanes = n / (H_DIM * W_DIM);  // B*C = 16

    dim3 grid(W4 / 256, H_DIM / RPT, nplanes);   // (2, 512, 16)
    stencil_poly_4row<<<grid, 256>>>(x, a, w, out);
}